// round 4
// baseline (speedup 1.0000x reference)
#include <cuda_runtime.h>
#include <math.h>

#define Nn 20000
#define IN_DIMc 1536
#define HIDc 256
#define HEADSc 4
#define HDc 64
#define HOPSc 3
#define NCLSc 3
#define EMAXc 400000
#define EPSV 1e-5f
#define NEG_SLOPE 0.2f

// ---------------- scratch (device globals; no allocations) ----------------
__device__ float g_X[Nn * HIDc];
__device__ float g_tmp[Nn * HIDc];
__device__ float g_XL[Nn * HIDc];
__device__ float g_XR[Nn * HIDc];
__device__ float g_logits[(EMAXc + Nn) * HEADSc];
__device__ float g_m[Nn * HEADSc];
__device__ float g_denom[Nn * HEADSc];
__device__ float g_gout[Nn * HIDc];
__device__ int g_flag;  // 1 = edge_index is int64, 0 = int32

// ---------------- utilities ----------------
__device__ __forceinline__ void atomicMaxF(float* addr, float v) {
    int old = __float_as_int(*addr);
    while (v > __int_as_float(old)) {
        int assumed = old;
        old = atomicCAS((int*)addr, assumed, __float_as_int(v));
        if (old == assumed) break;
    }
}

// Probe edge_index dtype: if the first 256 entries, read as int64, are all in
// [0, Nn), the buffer really is int64 (int32 data reinterpreted combines two
// random values -> >= 2^32 with overwhelming probability).
__global__ void detect_idx_kernel(const void* __restrict__ ei) {
    if (threadIdx.x == 0 && blockIdx.x == 0) {
        const long long* p = (const long long*)ei;
        int ok = 1;
        for (int i = 0; i < 256; i++) {
            long long v = p[i];
            if (v < 0 || v >= (long long)Nn) { ok = 0; break; }
        }
        g_flag = ok;
    }
}

__device__ __forceinline__ int edge_get(const void* ei, long long idx, int flag) {
    return flag ? (int)((const long long*)ei)[idx] : ((const int*)ei)[idx];
}

// ---------------- GEMM: C[M,Nc] = A[M,K] @ B[K,Nc] + bias ----------------
// BM=64, BN=64, BK=16, 256 threads, 4x4 micro-tile.
__global__ void gemm_bias_kernel(const float* __restrict__ A, const float* __restrict__ B,
                                 const float* __restrict__ bias, float* __restrict__ C,
                                 int M, int K, int Nc) {
    __shared__ float As[16][64];
    __shared__ float Bs[16][64];
    int tid = threadIdx.x;
    int tx = tid & 15, ty = tid >> 4;
    int bm = blockIdx.x, bn = blockIdx.y;

    float acc[4][4];
#pragma unroll
    for (int i = 0; i < 4; i++)
#pragma unroll
        for (int j = 0; j < 4; j++) acc[i][j] = 0.f;

    int ar = tid >> 2;            // 0..63 row within tile
    int akq = (tid & 3) * 4;      // k quad
    int arow = bm * 64 + ar;
    int brr = tid >> 4;           // 0..15 k row
    int bcol = bn * 64 + (tid & 15) * 4;

    for (int kt = 0; kt < K; kt += 16) {
        float4 a4 = make_float4(0.f, 0.f, 0.f, 0.f);
        if (arow < M) a4 = *(const float4*)(A + (long long)arow * K + kt + akq);
        As[akq + 0][ar] = a4.x;
        As[akq + 1][ar] = a4.y;
        As[akq + 2][ar] = a4.z;
        As[akq + 3][ar] = a4.w;
        float4 b4 = *(const float4*)(B + (long long)(kt + brr) * Nc + bcol);
        *(float4*)&Bs[brr][(tid & 15) * 4] = b4;
        __syncthreads();
#pragma unroll
        for (int k = 0; k < 16; k++) {
            float4 av = *(float4*)&As[k][ty * 4];
            float4 bv = *(float4*)&Bs[k][tx * 4];
            acc[0][0] += av.x * bv.x; acc[0][1] += av.x * bv.y; acc[0][2] += av.x * bv.z; acc[0][3] += av.x * bv.w;
            acc[1][0] += av.y * bv.x; acc[1][1] += av.y * bv.y; acc[1][2] += av.y * bv.z; acc[1][3] += av.y * bv.w;
            acc[2][0] += av.z * bv.x; acc[2][1] += av.z * bv.y; acc[2][2] += av.z * bv.z; acc[2][3] += av.z * bv.w;
            acc[3][0] += av.w * bv.x; acc[3][1] += av.w * bv.y; acc[3][2] += av.w * bv.z; acc[3][3] += av.w * bv.w;
        }
        __syncthreads();
    }

    int col = bn * 64 + tx * 4;
    float4 bb = *(const float4*)(bias + col);
#pragma unroll
    for (int i = 0; i < 4; i++) {
        int row = bm * 64 + ty * 4 + i;
        if (row < M) {
            float4 o;
            o.x = acc[i][0] + bb.x;
            o.y = acc[i][1] + bb.y;
            o.z = acc[i][2] + bb.z;
            o.w = acc[i][3] + bb.w;
            *(float4*)(C + (long long)row * Nc + col) = o;
        }
    }
}

// ---------------- block stats helper ----------------
__device__ __forceinline__ void block_mean_var_256(float v, float* smem, float& mu, float& var) {
    // smem must be at least 16 floats
    float s = v, sq = v * v;
#pragma unroll
    for (int o = 16; o > 0; o >>= 1) {
        s += __shfl_xor_sync(0xffffffffu, s, o);
        sq += __shfl_xor_sync(0xffffffffu, sq, o);
    }
    int w = threadIdx.x >> 5, l = threadIdx.x & 31;
    if (l == 0) { smem[w] = s; smem[8 + w] = sq; }
    __syncthreads();
    if (w == 0) {
        s = (l < 8) ? smem[l] : 0.f;
        sq = (l < 8) ? smem[8 + l] : 0.f;
#pragma unroll
        for (int o = 4; o > 0; o >>= 1) {
            s += __shfl_xor_sync(0xffffffffu, s, o);
            sq += __shfl_xor_sync(0xffffffffu, sq, o);
        }
        if (l == 0) { smem[0] = s; smem[8] = sq; }
    }
    __syncthreads();
    mu = smem[0] * (1.f / HIDc);
    var = smem[8] * (1.f / HIDc) - mu * mu;
}

__global__ void ln_kernel(const float* __restrict__ in, const float* __restrict__ g,
                          const float* __restrict__ b, float* __restrict__ out) {
    __shared__ float smem[16];
    int n = blockIdx.x, c = threadIdx.x;
    float v = in[(long long)n * HIDc + c];
    float mu, var;
    block_mean_var_256(v, smem, mu, var);
    out[(long long)n * HIDc + c] = (v - mu) * rsqrtf(var + EPSV) * g[c] + b[c];
}

// ---------------- per-hop segment buffers init ----------------
__global__ void init_seg_kernel() {
    int i = blockIdx.x * blockDim.x + threadIdx.x;
    if (i < Nn * HIDc) g_gout[i] = 0.f;
    if (i < Nn * HEADSc) { g_m[i] = -1e30f; g_denom[i] = 0.f; }
}

// ---------------- edge pass 1: logits + segment max ----------------
__global__ void edge_logits_kernel(const void* __restrict__ ei,
                                   const float* __restrict__ XL, const float* __restrict__ XR,
                                   const float* __restrict__ att,
                                   float* __restrict__ logits, float* __restrict__ m,
                                   int E, int etot) {
    int e = blockIdx.x * 8 + (threadIdx.x >> 5);
    if (e >= etot) return;
    int lane = threadIdx.x & 31;
    int flag = g_flag;
    int src, dst;
    if (e < E) {
        src = edge_get(ei, e, flag);
        dst = edge_get(ei, (long long)E + e, flag);
    } else {
        src = dst = e - E;
    }
    const float4* xl4 = (const float4*)(XL + (long long)src * HIDc);
    const float4* xr4 = (const float4*)(XR + (long long)dst * HIDc);
    int head = lane >> 3;
    float s = 0.f;
#pragma unroll
    for (int q = 0; q < 2; q++) {
        float4 a = xl4[lane * 2 + q];
        float4 b = xr4[lane * 2 + q];
        int cbase = lane * 8 + q * 4;
        const float* ap = att + head * HDc + (cbase & 63);
        float v;
        v = a.x + b.x; v = v > 0.f ? v : NEG_SLOPE * v; s += v * ap[0];
        v = a.y + b.y; v = v > 0.f ? v : NEG_SLOPE * v; s += v * ap[1];
        v = a.z + b.z; v = v > 0.f ? v : NEG_SLOPE * v; s += v * ap[2];
        v = a.w + b.w; v = v > 0.f ? v : NEG_SLOPE * v; s += v * ap[3];
    }
    s += __shfl_xor_sync(0xffffffffu, s, 1);
    s += __shfl_xor_sync(0xffffffffu, s, 2);
    s += __shfl_xor_sync(0xffffffffu, s, 4);
    if ((lane & 7) == 0) {
        logits[(long long)e * HEADSc + head] = s;
        atomicMaxF(&m[dst * HEADSc + head], s);
    }
}

// ---------------- edge pass 2: exp + denom + weighted scatter ----------------
__global__ void edge_scatter_kernel(const void* __restrict__ ei,
                                    const float* __restrict__ XL,
                                    const float* __restrict__ logits, const float* __restrict__ m,
                                    float* __restrict__ denom, float* __restrict__ gout,
                                    int E, int etot) {
    int e = blockIdx.x * 8 + (threadIdx.x >> 5);
    if (e >= etot) return;
    int lane = threadIdx.x & 31;
    int flag = g_flag;
    int src, dst;
    if (e < E) {
        src = edge_get(ei, e, flag);
        dst = edge_get(ei, (long long)E + e, flag);
    } else {
        src = dst = e - E;
    }
    float ex = 0.f;
    if (lane < HEADSc) {
        float lo = logits[(long long)e * HEADSc + lane];
        ex = __expf(lo - m[dst * HEADSc + lane]);
        atomicAdd(&denom[dst * HEADSc + lane], ex);
    }
    const float* xl = XL + (long long)src * HIDc;
    float* go = gout + (long long)dst * HIDc;
#pragma unroll
    for (int i = 0; i < 8; i++) {
        float w = __shfl_sync(0xffffffffu, ex, i >> 1);
        int c = i * 32 + lane;
        atomicAdd(&go[c], w * xl[c]);
    }
}

// ---------------- finalize: normalize, bias, residual, LN ----------------
__global__ void finalize_kernel(const float* __restrict__ gout, const float* __restrict__ denom,
                                const float* __restrict__ gbias,
                                const float* __restrict__ lng, const float* __restrict__ lnb,
                                float* __restrict__ X) {
    __shared__ float smem[16];
    int n = blockIdx.x, c = threadIdx.x;
    float v = gout[(long long)n * HIDc + c] / denom[n * HEADSc + (c >> 6)]
              + gbias[c] + X[(long long)n * HIDc + c];
    float mu, var;
    block_mean_var_256(v, smem, mu, var);
    X[(long long)n * HIDc + c] = (v - mu) * rsqrtf(var + EPSV) * lng[c] + lnb[c];
}

// ---------------- head: GELU(T) @ h2_W + h2_b, warp per node ----------------
__global__ void head2_kernel(const float* __restrict__ T, const float* __restrict__ W2,
                             const float* __restrict__ b2, float* __restrict__ out) {
    int n = blockIdx.x * 8 + (threadIdx.x >> 5);
    if (n >= Nn) return;
    int lane = threadIdx.x & 31;
    const float* t = T + (long long)n * HIDc;
    float a0 = 0.f, a1 = 0.f, a2 = 0.f;
#pragma unroll
    for (int j = 0; j < 8; j++) {
        int k = j * 32 + lane;
        float x = t[k];
        float ge = 0.5f * x * (1.f + erff(x * 0.70710678118654752440f));
        a0 += ge * W2[k * 3 + 0];
        a1 += ge * W2[k * 3 + 1];
        a2 += ge * W2[k * 3 + 2];
    }
#pragma unroll
    for (int o = 16; o > 0; o >>= 1) {
        a0 += __shfl_xor_sync(0xffffffffu, a0, o);
        a1 += __shfl_xor_sync(0xffffffffu, a1, o);
        a2 += __shfl_xor_sync(0xffffffffu, a2, o);
    }
    if (lane == 0) {
        out[n * 3 + 0] = a0 + b2[0];
        out[n * 3 + 1] = a1 + b2[1];
        out[n * 3 + 2] = a2 + b2[2];
    }
}

// ---------------- launcher ----------------
extern "C" void kernel_launch(void* const* d_in, const int* in_sizes, int n_in,
                              void* d_out, int out_size) {
    const float* features = (const float*)d_in[0];
    const void* ei = d_in[1];
    const float* proj_W = (const float*)d_in[2];
    const float* proj_b = (const float*)d_in[3];
    const float* n0_g = (const float*)d_in[4];
    const float* n0_b = (const float*)d_in[5];
    const float* Wl = (const float*)d_in[6];
    const float* bl = (const float*)d_in[7];
    const float* Wr = (const float*)d_in[8];
    const float* br = (const float*)d_in[9];
    const float* att = (const float*)d_in[10];
    const float* gbias = (const float*)d_in[11];
    const float* ln_g = (const float*)d_in[12];
    const float* ln_b = (const float*)d_in[13];
    const float* h1_W = (const float*)d_in[14];
    const float* h1_b = (const float*)d_in[15];
    const float* h2_W = (const float*)d_in[16];
    const float* h2_b = (const float*)d_in[17];
    float* out = (float*)d_out;

    int E = in_sizes[1] / 2;
    int etot = E + Nn;

    float *pX, *pTmp, *pXL, *pXR, *pLog, *pM, *pD, *pG;
    cudaGetSymbolAddress((void**)&pX, g_X);
    cudaGetSymbolAddress((void**)&pTmp, g_tmp);
    cudaGetSymbolAddress((void**)&pXL, g_XL);
    cudaGetSymbolAddress((void**)&pXR, g_XR);
    cudaGetSymbolAddress((void**)&pLog, g_logits);
    cudaGetSymbolAddress((void**)&pM, g_m);
    cudaGetSymbolAddress((void**)&pD, g_denom);
    cudaGetSymbolAddress((void**)&pG, g_gout);

    dim3 gemmGrid((Nn + 63) / 64, HIDc / 64);
    int edgeBlocks = (etot + 7) / 8;

    detect_idx_kernel<<<1, 32>>>(ei);

    // proj + input LN
    gemm_bias_kernel<<<gemmGrid, 256>>>(features, proj_W, proj_b, pTmp, Nn, IN_DIMc, HIDc);
    ln_kernel<<<Nn, 256>>>(pTmp, n0_g, n0_b, pX);

    for (int h = 0; h < HOPSc; h++) {
        const float* Wlh = Wl + (long long)h * HIDc * HIDc;
        const float* Wrh = Wr + (long long)h * HIDc * HIDc;
        gemm_bias_kernel<<<gemmGrid, 256>>>(pX, Wlh, bl + h * HIDc, pXL, Nn, HIDc, HIDc);
        gemm_bias_kernel<<<gemmGrid, 256>>>(pX, Wrh, br + h * HIDc, pXR, Nn, HIDc, HIDc);
        init_seg_kernel<<<(Nn * HIDc + 255) / 256, 256>>>();
        edge_logits_kernel<<<edgeBlocks, 256>>>(ei, pXL, pXR, att + h * HEADSc * HDc,
                                                pLog, pM, E, etot);
        edge_scatter_kernel<<<edgeBlocks, 256>>>(ei, pXL, pLog, pM, pD, pG, E, etot);
        finalize_kernel<<<Nn, 256>>>(pG, pD, gbias + h * HIDc,
                                     ln_g + h * HIDc, ln_b + h * HIDc, pX);
    }

    // head
    gemm_bias_kernel<<<gemmGrid, 256>>>(pX, h1_W, h1_b, pTmp, Nn, HIDc, HIDc);
    head2_kernel<<<(Nn + 7) / 8, 256>>>(pTmp, h2_W, h2_b, out);
}